// round 3
// baseline (speedup 1.0000x reference)
#include <cuda_runtime.h>

#define NSEG   8
#define KPTS   768
#define NMAPS  7
#define NPTS   (NSEG * KPTS)        // 6144
#define EPM    (KPTS * KPTS)        // 589824
#define ETOT   (NMAPS * EPM)        // 4128768

#define CHUNKS_PER_MAP 256
#define TOTAL_CHUNKS   (NMAPS * CHUNKS_PER_MAP)   // 1792
#define PIX_PER_CHUNK  (1048576 / CHUNKS_PER_MAP) // 4096 pixels
#define GRP_PER_CHUNK  (PIX_PER_CHUNK / 4)        // 1024 float4 groups
#define TILES          (NMAPS * KPTS)             // 5376

// Scratch: channel-interleaved PAF (m, y, x) -> (c0, c1), 56 MB
__device__ float2 g_paf[NMAPS * 1048576];
__device__ float2 g_tabA[NPTS];   // PAF of map seg(i) at point i   (x=0 sample == p1)
__device__ float2 g_tabB[NPTS];   // PAF of map seg(i)-1 at point i (x=9 sample == p2)

// Sync state (reset each launch by reset_kernel)
__device__ unsigned g_cnt[NMAPS];   // chunks repacked per map
__device__ unsigned g_tab;          // blocks done with table share
__device__ unsigned g_pticket;      // producer chunk queue
__device__ unsigned g_ticket;       // consumer tile queue

__global__ void reset_kernel() {
    int t = threadIdx.x;
    if (t < NMAPS) g_cnt[t] = 0;
    if (t == NMAPS)     g_tab = 0;
    if (t == NMAPS + 1) g_pticket = 0;
    if (t == NMAPS + 2) g_ticket = 0;
}

__global__ __launch_bounds__(256, 2)
void fused_kernel(const int* __restrict__ sk, const float* __restrict__ PAF,
                  float* __restrict__ out, int nblocks, int nprod) {
    const int bid = blockIdx.x;
    const int tid = threadIdx.x;

    // ---------- Phase 0: every block builds a strided share of the endpoint table ----------
    for (int i = bid * 256 + tid; i < NPTS; i += nblocks * 256) {
        int s = i / KPTS;
        int x = __ldg(&sk[3 * i + 1]);
        int y = __ldg(&sk[3 * i + 2]);
        int pix = (y << 10) + x;                   // row = coord1, col = coord0
        float2 va = make_float2(0.f, 0.f);
        float2 vb = make_float2(0.f, 0.f);
        if (s < NMAPS) {
            va.x = __ldg(&PAF[((size_t)(2 * s)     << 20) + pix]);
            va.y = __ldg(&PAF[((size_t)(2 * s + 1) << 20) + pix]);
        }
        if (s >= 1) {
            int m = s - 1;
            vb.x = __ldg(&PAF[((size_t)(2 * m)     << 20) + pix]);
            vb.y = __ldg(&PAF[((size_t)(2 * m + 1) << 20) + pix]);
        }
        g_tabA[i] = va;
        g_tabB[i] = vb;
    }
    __syncthreads();
    __threadfence();
    if (tid == 0) atomicAdd(&g_tab, 1);

    __shared__ unsigned s_t;

    // ---------- Phase 1: producer blocks repack chunks, map-major via ticket queue ----------
    if (bid < nprod) {
        for (;;) {
            if (tid == 0) s_t = atomicAdd(&g_pticket, 1);
            __syncthreads();
            unsigned c = s_t;
            __syncthreads();
            if (c >= TOTAL_CHUNKS) break;
            int m    = c >> 8;                     // c / CHUNKS_PER_MAP
            int part = c & (CHUNKS_PER_MAP - 1);
            const float4* c0p = (const float4*)(PAF + ((size_t)(2 * m)     << 20)) + part * GRP_PER_CHUNK;
            const float4* c1p = (const float4*)(PAF + ((size_t)(2 * m + 1) << 20)) + part * GRP_PER_CHUNK;
            float4* dst = (float4*)(g_paf + ((size_t)m << 20)) + (size_t)part * GRP_PER_CHUNK * 2;
#pragma unroll
            for (int g = tid; g < GRP_PER_CHUNK; g += 256) {
                float4 a = __ldg(&c0p[g]);
                float4 b = __ldg(&c1p[g]);
                dst[2 * g]     = make_float4(a.x, b.x, a.y, b.y);
                dst[2 * g + 1] = make_float4(a.z, b.z, a.w, b.w);
            }
            __syncthreads();
            __threadfence();
            if (tid == 0) atomicAdd(&g_cnt[m], 1);
        }
    }

    // ---------- Phase 2: all blocks consume edge tiles (m, a) via ticket queue ----------
    if (tid == 0) {
        while (*(volatile unsigned*)&g_tab < (unsigned)nblocks) __nanosleep(64);
    }
    __syncthreads();
    __threadfence();

    for (;;) {
        if (tid == 0) s_t = atomicAdd(&g_ticket, 1);
        __syncthreads();
        unsigned t = s_t;
        if (t >= TILES) break;
        int m = t / KPTS;
        int a = t - m * KPTS;
        if (tid == 0) {
            while (*(volatile unsigned*)&g_cnt[m] < (unsigned)CHUNKS_PER_MAP) __nanosleep(64);
        }
        __syncthreads();
        __threadfence();   // acquire: order g_paf reads after counter observation

        int i2  = (m + 1) * KPTS + a;
        int p2x = __ldg(&sk[3 * i2 + 1]);
        int p2y = __ldg(&sk[3 * i2 + 2]);
        float2 vB = g_tabB[i2];
        const float2* paf = g_paf + ((size_t)m << 20);

#pragma unroll
        for (int e = 0; e < 3; e++) {
            int b  = tid + e * 256;
            int i1 = m * KPTS + b;
            int p1x = __ldg(&sk[3 * i1 + 1]);
            int p1y = __ldg(&sk[3 * i1 + 2]);

            int dx = p2x - p1x;
            int dy = p2y - p1y;
            float fdx = (float)dx, fdy = (float)dy;
            float R = sqrtf(fdx * fdx + fdy * fdy);
            float2 vA = g_tabA[i1];

            // Interior samples x=1..8: pos = (p1*(9-x) + p2*x) // 9
            // n in [0, 9207]; floor(n/9) == (n*58255)>>19 exactly there.
            float2 v[8];
            int nx = p1x * 9, ny = p1y * 9;
#pragma unroll
            for (int s = 0; s < 8; s++) {
                nx += dx; ny += dy;
                int lx = (nx * 58255) >> 19;
                int ly = (ny * 58255) >> 19;
                v[s] = __ldg(&paf[(ly << 10) + lx]);
            }

            float sx = vA.x + vB.x;
            float sy = vA.y + vB.y;
#pragma unroll
            for (int s = 0; s < 8; s++) { sx += v[s].x; sy += v[s].y; }

            float acc = fdx * sx + fdy * sy;
            float li = (R > 0.f) ? (acc / (10.f * R)) : 0.f;   // NaN (R==0) -> 0

            int idx = m * EPM + a * KPTS + b;
            out[idx]            = (float)i1;
            out[ETOT + idx]     = (float)i2;
            out[2 * ETOT + idx] = li;
            out[3 * ETOT + idx] = R;
        }
    }
}

extern "C" void kernel_launch(void* const* d_in, const int* in_sizes, int n_in,
                              void* d_out, int out_size) {
    const int*   sk  = (const int*)d_in[0];     // skeletons: (6144, 3) int32 [seg, x, y]
    const float* PAF = (const float*)d_in[1];   // (7, 2, 1024, 1024) float32
    float* out = (float*)d_out;

    int nSM = 148;
    cudaDeviceGetAttribute(&nSM, cudaDevAttrMultiProcessorCount, 0);
    int nblocks = 2 * nSM;            // launch_bounds(256,2) guarantees full residency
    int nprod   = (2 * nblocks) / 3;  // producer share; producers join consumption after

    reset_kernel<<<1, 32>>>();
    fused_kernel<<<nblocks, 256>>>(sk, PAF, out, nblocks, nprod);
}

// round 4
// speedup vs baseline: 1.0355x; 1.0355x over previous
#include <cuda_runtime.h>

#define NSEG   8
#define KPTS   768
#define NMAPS  7
#define NPTS   (NSEG * KPTS)        // 6144
#define EPM    (KPTS * KPTS)        // 589824
#define ETOT   (NMAPS * EPM)        // 4128768

#define CHUNKS_PER_MAP 256
#define TOTAL_CHUNKS   (NMAPS * CHUNKS_PER_MAP)   // 1792
#define GRP_PER_CHUNK  (1048576 / CHUNKS_PER_MAP / 4)  // 1024 float4 groups / chunk
#define SUBT           (NMAPS * KPTS * 3)         // 16128 sub-tiles (256 edges each)

// Scratch: channel-interleaved PAF (m, y, x) -> (c0, c1), 56 MB
__device__ float2 g_paf[NMAPS * 1048576];
// Packed per-point records: {x, y, paf.x, paf.y} (paf floats bit-cast in .z/.w)
__device__ int4 g_ptA[NPTS];   // endpoint sample as p1 (map seg(i))
__device__ int4 g_ptB[NPTS];   // endpoint sample as p2 (map seg(i)-1)

// Sync state (reset each launch)
__device__ unsigned g_cnt[NMAPS];   // chunks repacked per map
__device__ unsigned g_tab;          // table-builder blocks done
__device__ unsigned g_pticket;      // producer chunk queue
__device__ unsigned g_ticket;       // consumer sub-tile queue

__global__ void reset_kernel() {
    int t = threadIdx.x;
    if (t < NMAPS) g_cnt[t] = 0;
    if (t == NMAPS)     g_tab = 0;
    if (t == NMAPS + 1) g_pticket = 0;
    if (t == NMAPS + 2) g_ticket = 0;
}

__global__ __launch_bounds__(256, 6)
void fused_kernel(const int* __restrict__ sk, const float* __restrict__ PAF,
                  float* __restrict__ out, int nblocks, int nprod, int ntabblk) {
    const int bid = blockIdx.x;
    const int tid = threadIdx.x;
    __shared__ unsigned s_t;

    // ---------- Phase 0: last ntabblk blocks build the packed point table ----------
    if (bid >= nblocks - ntabblk) {
        int i = (bid - (nblocks - ntabblk)) * 256 + tid;   // ntabblk*256 == NPTS
        if (i < NPTS) {
            int s = i / KPTS;
            int x = __ldg(&sk[3 * i + 1]);
            int y = __ldg(&sk[3 * i + 2]);
            int pix = (y << 10) + x;               // row = coord1, col = coord0
            float ax = 0.f, ay = 0.f, bx = 0.f, by = 0.f;
            if (s < NMAPS) {                       // used as p1 on map s
                ax = __ldg(&PAF[((size_t)(2 * s)     << 20) + pix]);
                ay = __ldg(&PAF[((size_t)(2 * s + 1) << 20) + pix]);
            }
            if (s >= 1) {                          // used as p2 on map s-1
                int m = s - 1;
                bx = __ldg(&PAF[((size_t)(2 * m)     << 20) + pix]);
                by = __ldg(&PAF[((size_t)(2 * m + 1) << 20) + pix]);
            }
            g_ptA[i] = make_int4(x, y, __float_as_int(ax), __float_as_int(ay));
            g_ptB[i] = make_int4(x, y, __float_as_int(bx), __float_as_int(by));
        }
        __syncthreads();
        __threadfence();
        if (tid == 0) atomicAdd(&g_tab, 1);
    }

    // ---------- Phase 1: producer blocks repack chunks, map-major ticket queue ----------
    if (bid < nprod) {
        for (;;) {
            if (tid == 0) s_t = atomicAdd(&g_pticket, 1);
            __syncthreads();
            unsigned c = s_t;
            __syncthreads();
            if (c >= TOTAL_CHUNKS) break;
            int m    = c >> 8;                     // c / CHUNKS_PER_MAP
            int part = c & (CHUNKS_PER_MAP - 1);
            const float4* c0p = (const float4*)(PAF + ((size_t)(2 * m)     << 20)) + part * GRP_PER_CHUNK;
            const float4* c1p = (const float4*)(PAF + ((size_t)(2 * m + 1) << 20)) + part * GRP_PER_CHUNK;
            float4* dst = (float4*)(g_paf + ((size_t)m << 20)) + (size_t)part * GRP_PER_CHUNK * 2;
#pragma unroll
            for (int g = tid; g < GRP_PER_CHUNK; g += 256) {
                float4 a = __ldg(&c0p[g]);
                float4 b = __ldg(&c1p[g]);
                dst[2 * g]     = make_float4(a.x, b.x, a.y, b.y);
                dst[2 * g + 1] = make_float4(a.z, b.z, a.w, b.w);
            }
            __syncthreads();
            __threadfence();
            if (tid == 0) atomicAdd(&g_cnt[m], 1);
        }
    }

    // ---------- Phase 2: all blocks consume 256-edge sub-tiles ----------
    if (tid == 0) {
        while (*(volatile unsigned*)&g_tab < (unsigned)ntabblk) __nanosleep(64);
    }
    __syncthreads();
    __threadfence();

    for (;;) {
        if (tid == 0) s_t = atomicAdd(&g_ticket, 1);
        __syncthreads();
        unsigned t = s_t;
        if (t >= SUBT) break;
        int m   = t / (KPTS * 3);
        int rem = t - m * (KPTS * 3);
        int a   = rem / 3;
        int b   = (rem - a * 3) * 256 + tid;

        if (tid == 0) {
            while (*(volatile unsigned*)&g_cnt[m] < (unsigned)CHUNKS_PER_MAP) __nanosleep(64);
        }
        __syncthreads();
        __threadfence();   // acquire: order g_paf reads after counter observation

        int i2 = (m + 1) * KPTS + a;     // p2 global point id (broadcast)
        int i1 = m * KPTS + b;           // p1 global point id

        int4 P2 = g_ptB[i2];
        int4 P1 = g_ptA[i1];
        int p2x = P2.x, p2y = P2.y;
        int p1x = P1.x, p1y = P1.y;

        int dx = p2x - p1x;
        int dy = p2y - p1y;
        float fdx = (float)dx, fdy = (float)dy;
        float R = sqrtf(fdx * fdx + fdy * fdy);

        const float2* paf = g_paf + ((size_t)m << 20);

        // Interior samples x=1..8: pos = (p1*(9-x) + p2*x) // 9
        // n in [0, 9207]; floor(n/9) == (n*58255)>>19 exactly there.
        float2 v[8];
        int nx = p1x * 9, ny = p1y * 9;
#pragma unroll
        for (int s = 0; s < 8; s++) {
            nx += dx; ny += dy;
            int lx = (nx * 58255) >> 19;
            int ly = (ny * 58255) >> 19;
            v[s] = __ldg(&paf[(ly << 10) + lx]);
        }

        float sx = __int_as_float(P1.z) + __int_as_float(P2.z);
        float sy = __int_as_float(P1.w) + __int_as_float(P2.w);
#pragma unroll
        for (int s = 0; s < 8; s++) { sx += v[s].x; sy += v[s].y; }

        float acc = fdx * sx + fdy * sy;
        float li = (R > 0.f) ? (acc / (10.f * R)) : 0.f;   // NaN (R==0) -> 0

        int idx = m * EPM + a * KPTS + b;
        out[idx]            = (float)i1;
        out[ETOT + idx]     = (float)i2;
        out[2 * ETOT + idx] = li;
        out[3 * ETOT + idx] = R;
    }
}

extern "C" void kernel_launch(void* const* d_in, const int* in_sizes, int n_in,
                              void* d_out, int out_size) {
    const int*   sk  = (const int*)d_in[0];     // skeletons: (6144, 3) int32 [seg, x, y]
    const float* PAF = (const float*)d_in[1];   // (7, 2, 1024, 1024) float32
    float* out = (float*)d_out;

    int nSM = 148;
    cudaDeviceGetAttribute(&nSM, cudaDevAttrMultiProcessorCount, 0);
    int nblocks = 6 * nSM;            // launch_bounds(256,6): all blocks co-resident
    int nprod   = nblocks / 4;        // ~25% of blocks repack (DRAM-bound, needs few)
    int ntabblk = NPTS / 256;         // 24 blocks build the point table

    reset_kernel<<<1, 32>>>();
    fused_kernel<<<nblocks, 256>>>(sk, PAF, out, nblocks, nprod, ntabblk);
}

// round 6
// speedup vs baseline: 1.1441x; 1.1049x over previous
#include <cuda_runtime.h>

#define NSEG   8
#define KPTS   768
#define NMAPS  7
#define NPTS   (NSEG * KPTS)        // 6144
#define EPM    (KPTS * KPTS)        // 589824
#define ETOT   (NMAPS * EPM)        // 4128768

#define REPACK_BLOCKS (NMAPS * 1048576 / 4 / 256)   // 7168
#define TABLE_BLOCKS  (NPTS / 256)                   // 24

// Scratch: channel-interleaved PAF (m, y, x) -> (c0, c1), 56 MB
__device__ float2 g_paf[NMAPS * 1048576];
// Packed per-point records: {x, y, paf.x, paf.y} (floats bit-cast into .z/.w)
__device__ int4 g_ptA[NPTS];   // endpoint sample as p1 (map seg(i):   x=0 sample == p1)
__device__ int4 g_ptB[NPTS];   // endpoint sample as p2 (map seg(i)-1: x=9 sample == p2)

// Repack (m, c, y, x) -> (m, y, x, c) float2, float4-vectorized (4 pixels/thread).
// Tail blocks build the packed endpoint table.
__global__ void prep_kernel(const int* __restrict__ sk, const float* __restrict__ PAF) {
    if (blockIdx.x < REPACK_BLOCKS) {
        int t    = blockIdx.x * 256 + threadIdx.x;     // one t per 4 pixels
        int m    = t / (1048576 / 4);
        int pix4 = t - m * (1048576 / 4);
        const float4* c0p = (const float4*)(PAF + ((size_t)(2 * m)     << 20));
        const float4* c1p = (const float4*)(PAF + ((size_t)(2 * m + 1) << 20));
        float4 c0 = __ldg(&c0p[pix4]);
        float4 c1 = __ldg(&c1p[pix4]);
        float2* dst = g_paf + ((size_t)m << 20) + (size_t)pix4 * 4;
        ((float4*)dst)[0] = make_float4(c0.x, c1.x, c0.y, c1.y);
        ((float4*)dst)[1] = make_float4(c0.z, c1.z, c0.w, c1.w);
    } else {
        int i = (blockIdx.x - REPACK_BLOCKS) * 256 + threadIdx.x;   // < NPTS
        int s = i / KPTS;
        int x = __ldg(&sk[3 * i + 1]);
        int y = __ldg(&sk[3 * i + 2]);
        int pix = (y << 10) + x;                   // row = coord1, col = coord0
        float ax = 0.f, ay = 0.f, bx = 0.f, by = 0.f;
        if (s < NMAPS) {                           // point used as p1 on map s
            ax = __ldg(&PAF[((size_t)(2 * s)     << 20) + pix]);
            ay = __ldg(&PAF[((size_t)(2 * s + 1) << 20) + pix]);
        }
        if (s >= 1) {                              // point used as p2 on map s-1
            int m = s - 1;
            bx = __ldg(&PAF[((size_t)(2 * m)     << 20) + pix]);
            by = __ldg(&PAF[((size_t)(2 * m + 1) << 20) + pix]);
        }
        g_ptA[i] = make_int4(x, y, __float_as_int(ax), __float_as_int(ay));
        g_ptB[i] = make_int4(x, y, __float_as_int(bx), __float_as_int(by));
    }
}

// One block per (map m, p2-index a); one thread per p1-index b.  (R2 structure.)
__global__ __launch_bounds__(KPTS) void paf_main_kernel(float* __restrict__ out) {
    int blk = blockIdx.x;
    int m = blk / KPTS;
    int a = blk - m * KPTS;
    int b = threadIdx.x;

    int i2 = (m + 1) * KPTS + a;     // p2 global point id (broadcast across block)
    int i1 = m * KPTS + b;           // p1 global point id (per-lane, coalesced)

    int4 P2 = __ldg(&g_ptB[i2]);
    int4 P1 = __ldg(&g_ptA[i1]);
    int p2x = P2.x, p2y = P2.y;
    int p1x = P1.x, p1y = P1.y;

    int dx = p2x - p1x;
    int dy = p2y - p1y;
    float fdx = (float)dx, fdy = (float)dy;
    float R = sqrtf(fdx * fdx + fdy * fdy);

    const float2* paf = g_paf + ((size_t)m << 20);

    // Interior samples x=1..8: pos = (p1*(9-x) + p2*x) // 9
    // n in [0, 9207]; floor(n/9) == (n*58255)>>19 exactly on that range.
    float2 v[8];
    int nx = p1x * 9, ny = p1y * 9;
#pragma unroll
    for (int s = 0; s < 8; s++) {
        nx += dx; ny += dy;
        int lx = (nx * 58255) >> 19;
        int ly = (ny * 58255) >> 19;
        v[s] = __ldg(&paf[(ly << 10) + lx]);
    }

    float sx = __int_as_float(P1.z) + __int_as_float(P2.z);   // x=0 and x=9 samples
    float sy = __int_as_float(P1.w) + __int_as_float(P2.w);
#pragma unroll
    for (int s = 0; s < 8; s++) { sx += v[s].x; sy += v[s].y; }

    float acc = fdx * sx + fdy * sy;
    float li = (R > 0.f) ? (acc / (10.f * R)) : 0.f;   // NaN (R==0) -> 0

    int idx = m * EPM + a * KPTS + b;
    // Output layout (float32): rows [i1 | i2 | li | R], each ETOT long
    out[idx]            = (float)i1;
    out[ETOT + idx]     = (float)i2;
    out[2 * ETOT + idx] = li;
    out[3 * ETOT + idx] = R;
}

extern "C" void kernel_launch(void* const* d_in, const int* in_sizes, int n_in,
                              void* d_out, int out_size) {
    const int*   sk  = (const int*)d_in[0];     // skeletons: (6144, 3) int32 [seg, x, y]
    const float* PAF = (const float*)d_in[1];   // (7, 2, 1024, 1024) float32
    float* out = (float*)d_out;

    prep_kernel<<<REPACK_BLOCKS + TABLE_BLOCKS, 256>>>(sk, PAF);
    paf_main_kernel<<<NMAPS * KPTS, KPTS>>>(out);
}

// round 7
// speedup vs baseline: 1.2267x; 1.0722x over previous
#include <cuda_runtime.h>
#include <cuda_fp16.h>

#define NSEG   8
#define KPTS   768
#define NMAPS  7
#define NPTS   (NSEG * KPTS)        // 6144
#define EPM    (KPTS * KPTS)        // 589824
#define ETOT   (NMAPS * EPM)        // 4128768

#define REPACK_BLOCKS (NMAPS * 1048576 / 4 / 256)   // 7168 (4 pixels/thread)
#define TABLE_BLOCKS  (NPTS / 256)                   // 24
#define SUBTILES      (NMAPS * KPTS * 3)             // 16128 (256 edges each)

// Scratch: channel-interleaved PAF in fp16: pixel -> half2(c0, c1), 28 MB
__device__ __half2 g_paf[NMAPS * 1048576];
// Packed per-point records: {x, y, paf.x, paf.y} (fp32 floats bit-cast into .z/.w)
__device__ int4 g_ptA[NPTS];   // endpoint sample as p1 (map seg(i):   x=0 sample == p1)
__device__ int4 g_ptB[NPTS];   // endpoint sample as p2 (map seg(i)-1: x=9 sample == p2)

// Repack (m, c, y, x) fp32 -> (m, y, x) half2(c0,c1); 4 pixels/thread, 16B stores.
// Tail blocks build the exact fp32 endpoint table.
__global__ void prep_kernel(const int* __restrict__ sk, const float* __restrict__ PAF) {
    if (blockIdx.x < REPACK_BLOCKS) {
        int t    = blockIdx.x * 256 + threadIdx.x;     // one t per 4 pixels
        int m    = t / (1048576 / 4);
        int pix4 = t - m * (1048576 / 4);
        const float4* c0p = (const float4*)(PAF + ((size_t)(2 * m)     << 20));
        const float4* c1p = (const float4*)(PAF + ((size_t)(2 * m + 1) << 20));
        float4 c0 = __ldg(&c0p[pix4]);
        float4 c1 = __ldg(&c1p[pix4]);
        __half2 h0 = __floats2half2_rn(c0.x, c1.x);
        __half2 h1 = __floats2half2_rn(c0.y, c1.y);
        __half2 h2 = __floats2half2_rn(c0.z, c1.z);
        __half2 h3 = __floats2half2_rn(c0.w, c1.w);
        uint4 pk;
        pk.x = *(unsigned*)&h0; pk.y = *(unsigned*)&h1;
        pk.z = *(unsigned*)&h2; pk.w = *(unsigned*)&h3;
        ((uint4*)(g_paf + ((size_t)m << 20)))[pix4] = pk;
    } else {
        int i = (blockIdx.x - REPACK_BLOCKS) * 256 + threadIdx.x;   // < NPTS
        int s = i / KPTS;
        int x = __ldg(&sk[3 * i + 1]);
        int y = __ldg(&sk[3 * i + 2]);
        int pix = (y << 10) + x;                   // row = coord1, col = coord0
        float ax = 0.f, ay = 0.f, bx = 0.f, by = 0.f;
        if (s < NMAPS) {                           // point used as p1 on map s
            ax = __ldg(&PAF[((size_t)(2 * s)     << 20) + pix]);
            ay = __ldg(&PAF[((size_t)(2 * s + 1) << 20) + pix]);
        }
        if (s >= 1) {                              // point used as p2 on map s-1
            int m = s - 1;
            bx = __ldg(&PAF[((size_t)(2 * m)     << 20) + pix]);
            by = __ldg(&PAF[((size_t)(2 * m + 1) << 20) + pix]);
        }
        g_ptA[i] = make_int4(x, y, __float_as_int(ax), __float_as_int(ay));
        g_ptB[i] = make_int4(x, y, __float_as_int(bx), __float_as_int(by));
    }
}

// One 256-thread block per third of a (map m, p2-index a) row -> 100% occupancy.
__global__ __launch_bounds__(256) void paf_main_kernel(float* __restrict__ out) {
    int t   = blockIdx.x;
    int m   = t / (KPTS * 3);
    int rem = t - m * (KPTS * 3);
    int a   = rem / 3;
    int b   = (rem - a * 3) * 256 + threadIdx.x;

    int i2 = (m + 1) * KPTS + a;     // p2 global point id (broadcast across block)
    int i1 = m * KPTS + b;           // p1 global point id (per-lane, coalesced)

    int4 P2 = __ldg(&g_ptB[i2]);
    int4 P1 = __ldg(&g_ptA[i1]);
    int p2x = P2.x, p2y = P2.y;
    int p1x = P1.x, p1y = P1.y;

    int dx = p2x - p1x;
    int dy = p2y - p1y;
    float fdx = (float)dx, fdy = (float)dy;
    float R = sqrtf(fdx * fdx + fdy * fdy);

    const __half2* paf = g_paf + ((size_t)m << 20);

    // Interior samples x=1..8: pos = (p1*(9-x) + p2*x) // 9
    // n in [0, 9207]; floor(n/9) == (n*58255)>>19 exactly on that range.
    __half2 v[8];
    int nx = p1x * 9, ny = p1y * 9;
#pragma unroll
    for (int s = 0; s < 8; s++) {
        nx += dx; ny += dy;
        int lx = (nx * 58255) >> 19;
        int ly = (ny * 58255) >> 19;
        v[s] = __ldg(&paf[(ly << 10) + lx]);
    }

    float sx = __int_as_float(P1.z) + __int_as_float(P2.z);   // exact x=0 / x=9 samples
    float sy = __int_as_float(P1.w) + __int_as_float(P2.w);
#pragma unroll
    for (int s = 0; s < 8; s++) {
        float2 f = __half22float2(v[s]);
        sx += f.x; sy += f.y;
    }

    float acc = fdx * sx + fdy * sy;
    float li = (R > 0.f) ? (acc / (10.f * R)) : 0.f;   // NaN (R==0) -> 0

    int idx = m * EPM + a * KPTS + b;
    // Output layout (float32): rows [i1 | i2 | li | R], each ETOT long
    out[idx]            = (float)i1;
    out[ETOT + idx]     = (float)i2;
    out[2 * ETOT + idx] = li;
    out[3 * ETOT + idx] = R;
}

extern "C" void kernel_launch(void* const* d_in, const int* in_sizes, int n_in,
                              void* d_out, int out_size) {
    const int*   sk  = (const int*)d_in[0];     // skeletons: (6144, 3) int32 [seg, x, y]
    const float* PAF = (const float*)d_in[1];   // (7, 2, 1024, 1024) float32
    float* out = (float*)d_out;

    prep_kernel<<<REPACK_BLOCKS + TABLE_BLOCKS, 256>>>(sk, PAF);
    paf_main_kernel<<<SUBTILES, 256>>>(out);
}